// round 10
// baseline (speedup 1.0000x reference)
#include <cuda_runtime.h>
#include <math.h>

// Problem constants
#define TN    8192
#define LOGN  13
#define HIDN  64
#define BN    8
#define CINN  32
#define COUTN 32
#define CTOTN 1024   // COUT*CIN
#define NFREQ 4097   // rfft bins
#define FSTR  4104   // padded row stride (complex), mult of 8

// padded smem index for FFT: one float2 of pad every 16
#define PADI(i) ((i) + ((i) >> 4))
#define SBUF 8704

typedef unsigned long long u64;

// ---------------- device scratch ------------------------------------------------
__device__ float2 d_tw[TN];                        // exp(-2*pi*i*k/N)
__device__ float  d_h2t[HIDN * TN];                // h2 transposed: [j][t]
__device__ float2 d_G[HIDN * FSTR];                // rfft(h2)
__device__ float2 d_Hf[(size_t)CTOTN * FSTR];      // filter spectra (half)
__device__ float2 d_Xf[(size_t)(BN * CINN) * FSTR];   // rfft(x)
__device__ float2 d_Yf[(size_t)(BN * COUTN) * FSTR];  // result spectra (half)

// ---------------- complex helpers -----------------------------------------------
__device__ __forceinline__ float2 cadd(float2 a, float2 b) { return make_float2(a.x + b.x, a.y + b.y); }
__device__ __forceinline__ float2 csub(float2 a, float2 b) { return make_float2(a.x - b.x, a.y - b.y); }
__device__ __forceinline__ float2 cmul(float2 a, float2 b) {
    return make_float2(a.x * b.x - a.y * b.y, a.x * b.y + a.y * b.x);
}

// ---------------- twiddle table -------------------------------------------------
__global__ void k_twiddle() {
    int k = blockIdx.x * blockDim.x + threadIdx.x;
    if (k < TN) {
        float s, c;
        sincospif(-2.0f * (float)k / (float)TN, &s, &c);
        d_tw[k] = make_float2(c, s);
    }
}

// ---------------- MLP -----------------------------------------------------------
__global__ void k_mlp(const float* __restrict__ w1, const float* __restrict__ b1,
                      const float* __restrict__ w2, const float* __restrict__ b2) {
    __shared__ float h1[4][HIDN];
    int g = threadIdx.x >> 6;
    int j = threadIdx.x & 63;
    int t = blockIdx.x * 4 + g;
    float pos = (float)t * (1.0f / (float)(TN - 1));
    float z = pos * w1[j] + b1[j];
    h1[g][j] = 0.5f * z * (1.0f + erff(z * 0.7071067811865476f));
    __syncthreads();
    float acc = b2[j];
#pragma unroll
    for (int k = 0; k < HIDN; k++) acc += h1[g][k] * w2[k * HIDN + j];
    float h2 = 0.5f * acc * (1.0f + erff(acc * 0.7071067811865476f));
    d_h2t[j * TN + t] = h2;
}

// ---------------- radix-8 Stockham FFT (8192 pts, 1024 threads) -----------------
__device__ __forceinline__ void dft8(const float2* v, float2* y) {
    const float S = 0.70710678118654752f;
    float2 a0 = cadd(v[0], v[4]), b0 = csub(v[0], v[4]);
    float2 a1 = cadd(v[1], v[5]), b1 = csub(v[1], v[5]);
    float2 a2 = cadd(v[2], v[6]), b2 = csub(v[2], v[6]);
    float2 a3 = cadd(v[3], v[7]), b3 = csub(v[3], v[7]);
    float2 c0 = cadd(a0, a2), c1 = csub(a0, a2);
    float2 c2 = cadd(a1, a3), c3 = csub(a1, a3);
    y[0] = cadd(c0, c2); y[4] = csub(c0, c2);
    float2 mc3 = make_float2(c3.y, -c3.x);
    y[2] = cadd(c1, mc3); y[6] = csub(c1, mc3);
    b1 = make_float2(S * (b1.x + b1.y), S * (b1.y - b1.x));
    b2 = make_float2(b2.y, -b2.x);
    b3 = make_float2(S * (b3.y - b3.x), -S * (b3.x + b3.y));
    float2 d0 = cadd(b0, b2), d1 = csub(b0, b2);
    float2 d2 = cadd(b1, b3), d3 = csub(b1, b3);
    y[1] = cadd(d0, d2); y[5] = csub(d0, d2);
    float2 md3 = make_float2(d3.y, -d3.x);
    y[3] = cadd(d1, md3); y[7] = csub(d1, md3);
}

template <int LS>
__device__ __forceinline__ void pass8(const float2* __restrict__ in,
                                      float2* __restrict__ out, int t) {
    int i = t;
    int j = i & (LS - 1);
    int base = ((i & ~(LS - 1)) << 3) | j;
    float2 v[8], y[8];
#pragma unroll
    for (int q = 0; q < 8; q++) v[q] = in[PADI(i + q * 1024)];
    if (LS > 1) {
#pragma unroll
        for (int q = 1; q < 8; q++)
            v[q] = cmul(v[q], d_tw[j * q * (1024 / LS)]);
    }
    dft8(v, y);
#pragma unroll
    for (int q = 0; q < 8; q++) out[PADI(base + q * LS)] = y[q];
}

__device__ __forceinline__ void fft_passes(float2* A, float2* B, int t) {
    pass8<1>(A, B, t);   __syncthreads();
    pass8<8>(B, A, t);   __syncthreads();
    pass8<64>(A, B, t);  __syncthreads();
    pass8<512>(B, A, t); __syncthreads();
#pragma unroll
    for (int u = 0; u < 4; u++) {
        int i = t + u * 1024;
        float2 a = A[PADI(i)];
        float2 b = cmul(A[PADI(i + 4096)], d_tw[i]);
        B[PADI(i)]        = cadd(a, b);
        B[PADI(i + 4096)] = csub(a, b);
    }
    __syncthreads();
}

// ---------------- forward FFTs: G rows (blocks 0..31) + x rows (32..159) --------
__global__ void __launch_bounds__(1024, 1)
k_fft_fwd(const float* __restrict__ x) {
    extern __shared__ float2 sm[];
    float2* A = sm;
    float2* B = sm + SBUF;
    int t = threadIdx.x;
    const float* ra;
    float2* oa;
    if (blockIdx.x < HIDN / 2) {
        ra = d_h2t + (size_t)(2 * blockIdx.x) * TN;
        oa = d_G   + (size_t)(2 * blockIdx.x) * FSTR;
    } else {
        int bb = blockIdx.x - HIDN / 2;
        ra = x    + (size_t)(2 * bb) * TN;
        oa = d_Xf + (size_t)(2 * bb) * FSTR;
    }
    const float* rb = ra + TN;
#pragma unroll
    for (int u = 0; u < 8; u++) {
        int idx = t + u * 1024;
        A[PADI(idx)] = make_float2(ra[idx], rb[idx]);
    }
    __syncthreads();
    fft_passes(A, B, t);
#pragma unroll
    for (int u = 0; u < 4; u++) {
        int f = t + u * 1024;
        float2 uu = B[PADI(f)];
        float2 vv = B[PADI((TN - f) & (TN - 1))];
        float vx = vv.x, vy = -vv.y;
        oa[f] = make_float2(0.5f * (uu.x + vx), 0.5f * (uu.y + vy));
        float wx = uu.x - vx, wyv = uu.y - vy;
        oa[FSTR + f] = make_float2(0.5f * wyv, -0.5f * wx);
    }
    if (t == 0) {
        float2 uu = B[PADI(TN / 2)];
        oa[TN / 2]        = make_float2(uu.x, 0.f);
        oa[FSTR + TN / 2] = make_float2(uu.y, 0.f);
    }
}

// ---------------- Hf GEMM: Hf[c][f] = sum_j w3[j][c] * G[j][f] ------------------
// Block: 128 c x 32 f. Threads 256 = 32 tc x 8 tf. Thread: 4c x 4f (f stride 8).
// w3 staged pre-duplicated {w,w} in smem; G staged as native u64 {re,im}.
// smem = 64*128*8 (w3d) + 64*32*8 (Gs) = 81920 B -> 2 blocks/SM.
#define HF_SM (64 * 128 * 8 + 64 * 32 * 8)

__global__ void __launch_bounds__(256, 2)
k_hf(const float* __restrict__ w3, const float* __restrict__ b3) {
    extern __shared__ __align__(16) char smraw[];
    u64* w3d = (u64*)smraw;            // [64 j][128 c]
    u64* Gs  = (u64*)smraw + 64 * 128; // [64 j][32 f]
    int f0 = blockIdx.x * 32;
    int c0 = blockIdx.y * 128;
    int tid = threadIdx.x;

    // stage w3 tile, duplicated to {w,w}
    for (int m = tid; m < 64 * 32; m += 256) {       // 2048 float4 groups
        int j = m >> 5, cq = m & 31;
        float4 w = *(const float4*)(w3 + (size_t)j * CTOTN + c0 + cq * 4);
        u64 d0, d1, d2, d3;
        asm("mov.b64 %0, {%1, %1};" : "=l"(d0) : "f"(w.x));
        asm("mov.b64 %0, {%1, %1};" : "=l"(d1) : "f"(w.y));
        asm("mov.b64 %0, {%1, %1};" : "=l"(d2) : "f"(w.z));
        asm("mov.b64 %0, {%1, %1};" : "=l"(d3) : "f"(w.w));
        u64* dst = w3d + j * 128 + cq * 4;
        dst[0] = d0; dst[1] = d1; dst[2] = d2; dst[3] = d3;
    }
    // stage G tile (zero-pad beyond NFREQ)
    for (int m = tid; m < 64 * 32; m += 256) {
        int j = m >> 5, f = m & 31;
        float2 g = (f0 + f < NFREQ) ? d_G[(size_t)j * FSTR + f0 + f]
                                    : make_float2(0.f, 0.f);
        u64 gv;
        asm("mov.b64 %0, {%1, %2};" : "=l"(gv) : "f"(g.x), "f"(g.y));
        Gs[j * 32 + f] = gv;
    }
    __syncthreads();

    int tc = tid >> 3;   // 0..31 -> c = c0 + tc*4 + cc
    int tf = tid & 7;    // 0..7  -> f = f0 + tf + 8k
    const u64* wrow = w3d + tc * 4;
    const u64* grow = Gs + tf;
    u64 acc[4][4];
#pragma unroll
    for (int cc = 0; cc < 4; cc++)
#pragma unroll
        for (int k = 0; k < 4; k++) acc[cc][k] = 0ull;

#pragma unroll 2
    for (int j = 0; j < 64; j++) {
        ulonglong2 w01 = *(const ulonglong2*)(wrow + j * 128);
        ulonglong2 w23 = *(const ulonglong2*)(wrow + j * 128 + 2);
        u64 g0 = grow[j * 32];
        u64 g1 = grow[j * 32 + 8];
        u64 g2 = grow[j * 32 + 16];
        u64 g3 = grow[j * 32 + 24];
        asm("fma.rn.f32x2 %0, %1, %2, %0;" : "+l"(acc[0][0]) : "l"(w01.x), "l"(g0));
        asm("fma.rn.f32x2 %0, %1, %2, %0;" : "+l"(acc[0][1]) : "l"(w01.x), "l"(g1));
        asm("fma.rn.f32x2 %0, %1, %2, %0;" : "+l"(acc[0][2]) : "l"(w01.x), "l"(g2));
        asm("fma.rn.f32x2 %0, %1, %2, %0;" : "+l"(acc[0][3]) : "l"(w01.x), "l"(g3));
        asm("fma.rn.f32x2 %0, %1, %2, %0;" : "+l"(acc[1][0]) : "l"(w01.y), "l"(g0));
        asm("fma.rn.f32x2 %0, %1, %2, %0;" : "+l"(acc[1][1]) : "l"(w01.y), "l"(g1));
        asm("fma.rn.f32x2 %0, %1, %2, %0;" : "+l"(acc[1][2]) : "l"(w01.y), "l"(g2));
        asm("fma.rn.f32x2 %0, %1, %2, %0;" : "+l"(acc[1][3]) : "l"(w01.y), "l"(g3));
        asm("fma.rn.f32x2 %0, %1, %2, %0;" : "+l"(acc[2][0]) : "l"(w23.x), "l"(g0));
        asm("fma.rn.f32x2 %0, %1, %2, %0;" : "+l"(acc[2][1]) : "l"(w23.x), "l"(g1));
        asm("fma.rn.f32x2 %0, %1, %2, %0;" : "+l"(acc[2][2]) : "l"(w23.x), "l"(g2));
        asm("fma.rn.f32x2 %0, %1, %2, %0;" : "+l"(acc[2][3]) : "l"(w23.x), "l"(g3));
        asm("fma.rn.f32x2 %0, %1, %2, %0;" : "+l"(acc[3][0]) : "l"(w23.y), "l"(g0));
        asm("fma.rn.f32x2 %0, %1, %2, %0;" : "+l"(acc[3][1]) : "l"(w23.y), "l"(g1));
        asm("fma.rn.f32x2 %0, %1, %2, %0;" : "+l"(acc[3][2]) : "l"(w23.y), "l"(g2));
        asm("fma.rn.f32x2 %0, %1, %2, %0;" : "+l"(acc[3][3]) : "l"(w23.y), "l"(g3));
    }

#pragma unroll
    for (int cc = 0; cc < 4; cc++) {
        int c = c0 + tc * 4 + cc;
        float bterm = (f0 == 0 && tf == 0) ? (float)TN * b3[c] : 0.f;
        float2* dst = d_Hf + (size_t)c * FSTR + f0 + tf;
#pragma unroll
        for (int k = 0; k < 4; k++) {
            int f = f0 + tf + 8 * k;
            if (f < NFREQ) {
                float2 v;
                asm("mov.b64 {%0, %1}, %2;" : "=f"(v.x), "=f"(v.y) : "l"(acc[cc][k]));
                if (k == 0) v.x += bterm;
                dst[8 * k] = v;
            }
        }
    }
}

// ---------------- contraction: Y[b,o,f] = sum_i X[b,i,f] * Hf[o*32+i,f] ---------
// No smem. Block: 16 freqs, 256 threads = (o = tid>>3, b = tid&7).
// Warp covers 4 o-rows x 8 b-rows -> L1 broadcast on both operand streams.
__global__ void __launch_bounds__(256)
k_contract() {
    int f0 = blockIdx.x * 16;
    int nf = NFREQ - f0; if (nf > 16) nf = 16;
    int tid = threadIdx.x;
    int o = tid >> 3, b = tid & 7;
    const float2* xbase = d_Xf + (size_t)(b * CINN) * FSTR + f0;
    const float2* hbase = d_Hf + (size_t)(o * CINN) * FSTR + f0;
    float2 acc[16];
#pragma unroll
    for (int f = 0; f < 16; f++) acc[f] = make_float2(0.f, 0.f);

    if (nf == 16) {
#pragma unroll 2
        for (int i = 0; i < CINN; i++) {
            const float4* xp = (const float4*)(xbase + (size_t)i * FSTR);
            const float4* hp = (const float4*)(hbase + (size_t)i * FSTR);
#pragma unroll
            for (int h = 0; h < 2; h++) {   // two f-halves of 8 to bound live regs
                float4 xq[4], hq[4];
#pragma unroll
                for (int q = 0; q < 4; q++) { xq[q] = xp[h * 4 + q]; hq[q] = hp[h * 4 + q]; }
#pragma unroll
                for (int q = 0; q < 4; q++) {
                    float2 x0 = make_float2(xq[q].x, xq[q].y);
                    float2 x1 = make_float2(xq[q].z, xq[q].w);
                    float2 h0 = make_float2(hq[q].x, hq[q].y);
                    float2 h1 = make_float2(hq[q].z, hq[q].w);
                    int fbase = h * 8 + q * 2;
                    acc[fbase].x     += x0.x * h0.x - x0.y * h0.y;
                    acc[fbase].y     += x0.x * h0.y + x0.y * h0.x;
                    acc[fbase + 1].x += x1.x * h1.x - x1.y * h1.y;
                    acc[fbase + 1].y += x1.x * h1.y + x1.y * h1.x;
                }
            }
        }
    } else {
        for (int i = 0; i < CINN; i++) {
            const float2* xp = xbase + (size_t)i * FSTR;
            const float2* hp = hbase + (size_t)i * FSTR;
#pragma unroll
            for (int f = 0; f < 16; f++) {
                if (f < nf) {
                    float2 xv = xp[f], hv = hp[f];
                    acc[f].x += xv.x * hv.x - xv.y * hv.y;
                    acc[f].y += xv.x * hv.y + xv.y * hv.x;
                }
            }
        }
    }
    float2* yr = d_Yf + (size_t)(b * COUTN + o) * FSTR + f0;
#pragma unroll
    for (int f = 0; f < 16; f++)
        if (f < nf) yr[f] = acc[f];
}

// ---------------- packed inverse FFT via conj(forward(conj)) --------------------
__global__ void __launch_bounds__(1024, 1)
k_fft_inv(float* __restrict__ out, const float* __restrict__ bias) {
    extern __shared__ float2 sm[];
    float2* A = sm;
    float2* B = sm + SBUF;
    int t = threadIdx.x;
    int b = blockIdx.x >> 4, q = blockIdx.x & 15;
    int oc = 2 * q;
    const float2* ra = d_Yf + (size_t)(b * COUTN + oc) * FSTR;
    const float2* rb = ra + FSTR;
#pragma unroll
    for (int u = 0; u < 4; u++) {
        int f = t + u * 1024;
        float2 Ya = ra[f], Yb = rb[f];
        A[PADI(f)] = make_float2(Ya.x - Yb.y, -(Ya.y + Yb.x));
        if (f > 0)
            A[PADI(TN - f)] = make_float2(Ya.x + Yb.y, Ya.y - Yb.x);
    }
    if (t == 0) {
        float2 Ya = ra[TN / 2], Yb = rb[TN / 2];
        A[PADI(TN / 2)] = make_float2(Ya.x - Yb.y, -(Ya.y + Yb.x));
    }
    __syncthreads();
    fft_passes(A, B, t);
    const float sc = 1.0f / (float)TN;
    float ba = bias[oc], bb = bias[oc + 1];
    float* pa = out + (size_t)(b * COUTN + oc) * TN;
    float* pb = pa + TN;
#pragma unroll
    for (int u = 0; u < 8; u++) {
        int i = t + u * 1024;
        float2 v = B[PADI(i)];
        pa[i] =  v.x * sc + ba;
        pb[i] = -v.y * sc + bb;
    }
}

// ---------------- launch --------------------------------------------------------
extern "C" void kernel_launch(void* const* d_in, const int* in_sizes, int n_in,
                              void* d_out, int out_size) {
    const float* x    = (const float*)d_in[0];
    const float* w1   = (const float*)d_in[1];
    const float* b1   = (const float*)d_in[2];
    const float* w2   = (const float*)d_in[3];
    const float* b2   = (const float*)d_in[4];
    const float* w3   = (const float*)d_in[5];
    const float* b3   = (const float*)d_in[6];
    const float* bias = (const float*)d_in[7];
    float* out = (float*)d_out;

    const int fftSm = 2 * SBUF * (int)sizeof(float2);   // 139264

    cudaFuncSetAttribute(k_fft_fwd, cudaFuncAttributeMaxDynamicSharedMemorySize, fftSm);
    cudaFuncSetAttribute(k_fft_inv, cudaFuncAttributeMaxDynamicSharedMemorySize, fftSm);
    cudaFuncSetAttribute(k_hf,      cudaFuncAttributeMaxDynamicSharedMemorySize, HF_SM);

    k_twiddle<<<32, 256>>>();
    k_mlp<<<TN / 4, 256>>>(w1, b1, w2, b2);
    k_fft_fwd<<<HIDN / 2 + BN * CINN / 2, 1024, fftSm>>>(x);
    k_hf<<<dim3(129, 8), 256, HF_SM>>>(w3, b3);
    k_contract<<<257, 256>>>();
    k_fft_inv<<<BN * COUTN / 2, 1024, fftSm>>>(out, bias);
}

// round 11
// speedup vs baseline: 1.6008x; 1.6008x over previous
#include <cuda_runtime.h>
#include <math.h>

// Problem constants
#define TN    8192
#define LOGN  13
#define HIDN  64
#define BN    8
#define CINN  32
#define COUTN 32
#define CTOTN 1024   // COUT*CIN
#define NFREQ 4097   // rfft bins
#define FSTR  4104   // padded row stride (complex), mult of 8

// padded smem index for FFT: one float2 of pad every 16
#define PADI(i) ((i) + ((i) >> 4))
#define SBUF 8704                       // padded float2 count for 8192
#define FFT_SM (SBUF * 8)               // 69632 bytes, single buffer

typedef unsigned long long u64;

// ---------------- device scratch ------------------------------------------------
__device__ float2 d_tw[TN];                        // exp(-2*pi*i*k/N)
__device__ float  d_h2t[HIDN * TN];                // h2 transposed: [j][t]
__device__ float2 d_G[HIDN * FSTR];                // rfft(h2)
__device__ float2 d_Xf[(size_t)(BN * CINN) * FSTR];   // rfft(x)
__device__ float2 d_Yf[(size_t)(BN * COUTN) * FSTR];  // result spectra (half)

// ---------------- complex helpers -----------------------------------------------
__device__ __forceinline__ float2 cadd(float2 a, float2 b) { return make_float2(a.x + b.x, a.y + b.y); }
__device__ __forceinline__ float2 csub(float2 a, float2 b) { return make_float2(a.x - b.x, a.y - b.y); }
__device__ __forceinline__ float2 cmul(float2 a, float2 b) {
    return make_float2(a.x * b.x - a.y * b.y, a.x * b.y + a.y * b.x);
}

// ---------------- twiddle table -------------------------------------------------
__global__ void k_twiddle() {
    int k = blockIdx.x * blockDim.x + threadIdx.x;
    if (k < TN) {
        float s, c;
        sincospif(-2.0f * (float)k / (float)TN, &s, &c);
        d_tw[k] = make_float2(c, s);
    }
}

// ---------------- MLP -----------------------------------------------------------
__global__ void k_mlp(const float* __restrict__ w1, const float* __restrict__ b1,
                      const float* __restrict__ w2, const float* __restrict__ b2) {
    __shared__ float h1[4][HIDN];
    int g = threadIdx.x >> 6;
    int j = threadIdx.x & 63;
    int t = blockIdx.x * 4 + g;
    float pos = (float)t * (1.0f / (float)(TN - 1));
    float z = pos * w1[j] + b1[j];
    h1[g][j] = 0.5f * z * (1.0f + erff(z * 0.7071067811865476f));
    __syncthreads();
    float acc = b2[j];
#pragma unroll
    for (int k = 0; k < HIDN; k++) acc += h1[g][k] * w2[k * HIDN + j];
    float h2 = 0.5f * acc * (1.0f + erff(acc * 0.7071067811865476f));
    d_h2t[j * TN + t] = h2;
}

// ---------------- radix-8 Stockham FFT, in-place smem, 512 threads --------------
__device__ __forceinline__ void dft8(const float2* v, float2* y) {
    const float S = 0.70710678118654752f;
    float2 a0 = cadd(v[0], v[4]), b0 = csub(v[0], v[4]);
    float2 a1 = cadd(v[1], v[5]), b1 = csub(v[1], v[5]);
    float2 a2 = cadd(v[2], v[6]), b2 = csub(v[2], v[6]);
    float2 a3 = cadd(v[3], v[7]), b3 = csub(v[3], v[7]);
    float2 c0 = cadd(a0, a2), c1 = csub(a0, a2);
    float2 c2 = cadd(a1, a3), c3 = csub(a1, a3);
    y[0] = cadd(c0, c2); y[4] = csub(c0, c2);
    float2 mc3 = make_float2(c3.y, -c3.x);
    y[2] = cadd(c1, mc3); y[6] = csub(c1, mc3);
    b1 = make_float2(S * (b1.x + b1.y), S * (b1.y - b1.x));
    b2 = make_float2(b2.y, -b2.x);
    b3 = make_float2(S * (b3.y - b3.x), -S * (b3.x + b3.y));
    float2 d0 = cadd(b0, b2), d1 = csub(b0, b2);
    float2 d2 = cadd(b1, b3), d3 = csub(b1, b3);
    y[1] = cadd(d0, d2); y[5] = csub(d0, d2);
    float2 md3 = make_float2(d3.y, -d3.x);
    y[3] = cadd(d1, md3); y[7] = csub(d1, md3);
}

// one radix-8 pass, in-place: read-all -> sync -> write-all -> sync
template <int LS>
__device__ __forceinline__ void pass8ip(float2* A, int t) {
    float2 v[2][8];
#pragma unroll
    for (int u = 0; u < 2; u++) {
        int i = t + u * 512;
        int j = i & (LS - 1);
#pragma unroll
        for (int q = 0; q < 8; q++) v[u][q] = A[PADI(i + q * 1024)];
        if (LS > 1) {
#pragma unroll
            for (int q = 1; q < 8; q++)
                v[u][q] = cmul(v[u][q], d_tw[j * q * (1024 / LS)]);
        }
    }
    __syncthreads();
#pragma unroll
    for (int u = 0; u < 2; u++) {
        int i = t + u * 512;
        int j = i & (LS - 1);
        int base = ((i & ~(LS - 1)) << 3) | j;
        float2 y[8];
        dft8(v[u], y);
#pragma unroll
        for (int q = 0; q < 8; q++) A[PADI(base + q * LS)] = y[q];
    }
    __syncthreads();
}

__device__ __forceinline__ void fft_passes_ip(float2* A, int t) {
    pass8ip<1>(A, t);
    pass8ip<8>(A, t);
    pass8ip<64>(A, t);
    pass8ip<512>(A, t);
    // final radix-2 is naturally in-place (writes == reads)
#pragma unroll
    for (int u = 0; u < 8; u++) {
        int i = t + u * 512;
        float2 a = A[PADI(i)];
        float2 b = cmul(A[PADI(i + 4096)], d_tw[i]);
        A[PADI(i)]        = cadd(a, b);
        A[PADI(i + 4096)] = csub(a, b);
    }
    __syncthreads();
}

// ---------------- forward FFTs: G rows (blocks 0..31) + x rows (32..159) --------
__global__ void __launch_bounds__(512, 2)
k_fft_fwd(const float* __restrict__ x) {
    extern __shared__ float2 A[];
    int t = threadIdx.x;
    const float* ra;
    float2* oa;
    if (blockIdx.x < HIDN / 2) {
        ra = d_h2t + (size_t)(2 * blockIdx.x) * TN;
        oa = d_G   + (size_t)(2 * blockIdx.x) * FSTR;
    } else {
        int bb = blockIdx.x - HIDN / 2;
        ra = x    + (size_t)(2 * bb) * TN;
        oa = d_Xf + (size_t)(2 * bb) * FSTR;
    }
    const float* rb = ra + TN;
#pragma unroll
    for (int u = 0; u < 16; u++) {
        int idx = t + u * 512;
        A[PADI(idx)] = make_float2(ra[idx], rb[idx]);
    }
    __syncthreads();
    fft_passes_ip(A, t);
    // unpack two real spectra, store f = 0..4096
#pragma unroll
    for (int u = 0; u < 8; u++) {
        int f = t + u * 512;
        float2 uu = A[PADI(f)];
        float2 vv = A[PADI((TN - f) & (TN - 1))];
        float vx = vv.x, vy = -vv.y;
        oa[f] = make_float2(0.5f * (uu.x + vx), 0.5f * (uu.y + vy));
        float wx = uu.x - vx, wyv = uu.y - vy;
        oa[FSTR + f] = make_float2(0.5f * wyv, -0.5f * wx);
    }
    if (t == 0) {
        float2 uu = A[PADI(TN / 2)];
        oa[TN / 2]        = make_float2(uu.x, 0.f);
        oa[FSTR + TN / 2] = make_float2(uu.y, 0.f);
    }
}

// ---------------- fused Hf-GEMM + contraction -----------------------------------
// Block: c-tile 128 (= 4 o x 32 i), f-tile 32. Grid (129 f, 8 o-groups).
// Phase1 (k_hf layout, measured 46.8us): M[c][f] = sum_j w3[j][c]*G[j][f] in regs.
// Handoff: regs -> Ms smem (overwrites w3 staging). Phase2: stage X half-tiles,
// Y[b,o,f] = sum_i X[b,i,f]*M[o*32+i][f] -> d_Yf directly. No Hf in gmem.
// smem: phase1 w3d 64KB + Gs 16KB = 80KB; phase2 Ms 34816 + Xs 36864 = 71680.
#define HFC_SM (64 * 128 * 8 + 64 * 32 * 8)   // 81920

__global__ void __launch_bounds__(256, 2)
k_hfc(const float* __restrict__ w3, const float* __restrict__ b3) {
    extern __shared__ __align__(16) char smraw[];
    u64* w3d = (u64*)smraw;            // [64 j][128 c] duplicated {w,w}
    u64* Gs  = (u64*)smraw + 64 * 128; // [64 j][32 f]
    int f0 = blockIdx.x * 32;
    int c0 = blockIdx.y * 128;
    int tid = threadIdx.x;

    // ---- stage w3 (duplicated) + G ----
    for (int m = tid; m < 64 * 32; m += 256) {
        int j = m >> 5, cq = m & 31;
        float4 w = *(const float4*)(w3 + (size_t)j * CTOTN + c0 + cq * 4);
        u64 d0, d1, d2, d3;
        asm("mov.b64 %0, {%1, %1};" : "=l"(d0) : "f"(w.x));
        asm("mov.b64 %0, {%1, %1};" : "=l"(d1) : "f"(w.y));
        asm("mov.b64 %0, {%1, %1};" : "=l"(d2) : "f"(w.z));
        asm("mov.b64 %0, {%1, %1};" : "=l"(d3) : "f"(w.w));
        u64* dst = w3d + j * 128 + cq * 4;
        dst[0] = d0; dst[1] = d1; dst[2] = d2; dst[3] = d3;
    }
    for (int m = tid; m < 64 * 32; m += 256) {
        int j = m >> 5, f = m & 31;
        float2 g = (f0 + f < NFREQ) ? d_G[(size_t)j * FSTR + f0 + f]
                                    : make_float2(0.f, 0.f);
        u64 gv;
        asm("mov.b64 %0, {%1, %2};" : "=l"(gv) : "f"(g.x), "f"(g.y));
        Gs[j * 32 + f] = gv;
    }
    __syncthreads();

    // ---- phase 1: thread = 4c x 4f, f stride 8 ----
    int tc = tid >> 3;   // 0..31
    int tf = tid & 7;    // 0..7
    const u64* wrow = w3d + tc * 4;
    const u64* grow = Gs + tf;
    u64 acc[4][4];
#pragma unroll
    for (int cc = 0; cc < 4; cc++)
#pragma unroll
        for (int k = 0; k < 4; k++) acc[cc][k] = 0ull;

#pragma unroll 2
    for (int j = 0; j < 64; j++) {
        ulonglong2 w01 = *(const ulonglong2*)(wrow + j * 128);
        ulonglong2 w23 = *(const ulonglong2*)(wrow + j * 128 + 2);
        u64 g0 = grow[j * 32];
        u64 g1 = grow[j * 32 + 8];
        u64 g2 = grow[j * 32 + 16];
        u64 g3 = grow[j * 32 + 24];
        asm("fma.rn.f32x2 %0, %1, %2, %0;" : "+l"(acc[0][0]) : "l"(w01.x), "l"(g0));
        asm("fma.rn.f32x2 %0, %1, %2, %0;" : "+l"(acc[0][1]) : "l"(w01.x), "l"(g1));
        asm("fma.rn.f32x2 %0, %1, %2, %0;" : "+l"(acc[0][2]) : "l"(w01.x), "l"(g2));
        asm("fma.rn.f32x2 %0, %1, %2, %0;" : "+l"(acc[0][3]) : "l"(w01.x), "l"(g3));
        asm("fma.rn.f32x2 %0, %1, %2, %0;" : "+l"(acc[1][0]) : "l"(w01.y), "l"(g0));
        asm("fma.rn.f32x2 %0, %1, %2, %0;" : "+l"(acc[1][1]) : "l"(w01.y), "l"(g1));
        asm("fma.rn.f32x2 %0, %1, %2, %0;" : "+l"(acc[1][2]) : "l"(w01.y), "l"(g2));
        asm("fma.rn.f32x2 %0, %1, %2, %0;" : "+l"(acc[1][3]) : "l"(w01.y), "l"(g3));
        asm("fma.rn.f32x2 %0, %1, %2, %0;" : "+l"(acc[2][0]) : "l"(w23.x), "l"(g0));
        asm("fma.rn.f32x2 %0, %1, %2, %0;" : "+l"(acc[2][1]) : "l"(w23.x), "l"(g1));
        asm("fma.rn.f32x2 %0, %1, %2, %0;" : "+l"(acc[2][2]) : "l"(w23.x), "l"(g2));
        asm("fma.rn.f32x2 %0, %1, %2, %0;" : "+l"(acc[2][3]) : "l"(w23.x), "l"(g3));
        asm("fma.rn.f32x2 %0, %1, %2, %0;" : "+l"(acc[3][0]) : "l"(w23.y), "l"(g0));
        asm("fma.rn.f32x2 %0, %1, %2, %0;" : "+l"(acc[3][1]) : "l"(w23.y), "l"(g1));
        asm("fma.rn.f32x2 %0, %1, %2, %0;" : "+l"(acc[3][2]) : "l"(w23.y), "l"(g2));
        asm("fma.rn.f32x2 %0, %1, %2, %0;" : "+l"(acc[3][3]) : "l"(w23.y), "l"(g3));
    }
    __syncthreads();   // all phase-1 smem reads complete; safe to overwrite

    // ---- handoff: regs -> Ms [128 rows][34], rows local c (o_loc = r>>5) ----
    float2* Ms = (float2*)smraw;               // 34816 bytes
    float2* Xs = (float2*)(smraw + 34816);     // [256 rows (b*32+i)][18]
#pragma unroll
    for (int cc = 0; cc < 4; cc++) {
        int r = tc * 4 + cc;
        float dc = (f0 == 0 && tf == 0) ? (float)TN * b3[c0 + r] : 0.f;
#pragma unroll
        for (int k = 0; k < 4; k++) {
            float2 v;
            asm("mov.b64 {%0, %1}, %2;" : "=f"(v.x), "=f"(v.y) : "l"(acc[cc][k]));
            if (k == 0) v.x += dc;
            Ms[r * 34 + tf + 8 * k] = v;
        }
    }
    // stage X half h=0 (16 freqs) — one row (b*32+i) per thread
    {
        const float2* xr = d_Xf + (size_t)tid * FSTR + f0;
        float2* xd = Xs + tid * 18;
#pragma unroll
        for (int f = 0; f < 16; f++)
            xd[f] = (f0 + f < NFREQ) ? xr[f] : make_float2(0.f, 0.f);
    }
    __syncthreads();

    // ---- phase 2: thread = (o, b, fq) -> Y[b][o][2 freqs] ----
    int o  = tid >> 6;
    int b  = (tid >> 3) & 7;
    int fq = tid & 7;
    int og = blockIdx.y * 4 + o;
#pragma unroll 1
    for (int h = 0; h < 2; h++) {
        if (h == 1) {
            __syncthreads();    // phase-2 h=0 reads done
            const float2* xr = d_Xf + (size_t)tid * FSTR + f0 + 16;
            float2* xd = Xs + tid * 18;
#pragma unroll
            for (int f = 0; f < 16; f++)
                xd[f] = (f0 + 16 + f < NFREQ) ? xr[f] : make_float2(0.f, 0.f);
            __syncthreads();
        }
        float2 a0 = make_float2(0.f, 0.f), a1 = make_float2(0.f, 0.f);
        const float2* mrow = Ms + (o * 32) * 34 + h * 16 + fq * 2;
        const float2* xrow = Xs + (b * 32) * 18 + fq * 2;
#pragma unroll 4
        for (int i = 0; i < 32; i++) {
            float4 xv = *(const float4*)(xrow + i * 18);
            float4 mv = *(const float4*)(mrow + i * 34);
            a0.x += xv.x * mv.x - xv.y * mv.y;
            a0.y += xv.x * mv.y + xv.y * mv.x;
            a1.x += xv.z * mv.z - xv.w * mv.w;
            a1.y += xv.z * mv.w + xv.w * mv.z;
        }
        int f = f0 + h * 16 + fq * 2;
        float2* yr = d_Yf + (size_t)(b * COUTN + og) * FSTR + f;
        if (f < NFREQ)     yr[0] = a0;
        if (f + 1 < NFREQ) yr[1] = a1;
    }
}

// ---------------- packed inverse FFT via conj(forward(conj)) --------------------
__global__ void __launch_bounds__(512, 2)
k_fft_inv(float* __restrict__ out, const float* __restrict__ bias) {
    extern __shared__ float2 A[];
    int t = threadIdx.x;
    int b = blockIdx.x >> 4, q = blockIdx.x & 15;
    int oc = 2 * q;
    const float2* ra = d_Yf + (size_t)(b * COUTN + oc) * FSTR;
    const float2* rb = ra + FSTR;
#pragma unroll
    for (int u = 0; u < 8; u++) {
        int f = t + u * 512;
        float2 Ya = ra[f], Yb = rb[f];
        A[PADI(f)] = make_float2(Ya.x - Yb.y, -(Ya.y + Yb.x));
        if (f > 0)
            A[PADI(TN - f)] = make_float2(Ya.x + Yb.y, Ya.y - Yb.x);
    }
    if (t == 0) {
        float2 Ya = ra[TN / 2], Yb = rb[TN / 2];
        A[PADI(TN / 2)] = make_float2(Ya.x - Yb.y, -(Ya.y + Yb.x));
    }
    __syncthreads();
    fft_passes_ip(A, t);
    const float sc = 1.0f / (float)TN;
    float ba = bias[oc], bb = bias[oc + 1];
    float* pa = out + (size_t)(b * COUTN + oc) * TN;
    float* pb = pa + TN;
#pragma unroll
    for (int u = 0; u < 16; u++) {
        int i = t + u * 512;
        float2 v = A[PADI(i)];
        pa[i] =  v.x * sc + ba;
        pb[i] = -v.y * sc + bb;
    }
}

// ---------------- launch --------------------------------------------------------
extern "C" void kernel_launch(void* const* d_in, const int* in_sizes, int n_in,
                              void* d_out, int out_size) {
    const float* x    = (const float*)d_in[0];
    const float* w1   = (const float*)d_in[1];
    const float* b1   = (const float*)d_in[2];
    const float* w2   = (const float*)d_in[3];
    const float* b2   = (const float*)d_in[4];
    const float* w3   = (const float*)d_in[5];
    const float* b3   = (const float*)d_in[6];
    const float* bias = (const float*)d_in[7];
    float* out = (float*)d_out;

    cudaFuncSetAttribute(k_fft_fwd, cudaFuncAttributeMaxDynamicSharedMemorySize, FFT_SM);
    cudaFuncSetAttribute(k_fft_inv, cudaFuncAttributeMaxDynamicSharedMemorySize, FFT_SM);
    cudaFuncSetAttribute(k_hfc,     cudaFuncAttributeMaxDynamicSharedMemorySize, HFC_SM);

    k_twiddle<<<32, 256>>>();
    k_mlp<<<TN / 4, 256>>>(w1, b1, w2, b2);
    k_fft_fwd<<<HIDN / 2 + BN * CINN / 2, 512, FFT_SM>>>(x);
    k_hfc<<<dim3(129, 8), 256, HFC_SM>>>(w3, b3);
    k_fft_inv<<<BN * COUTN / 2, 512, FFT_SM>>>(out, bias);
}